// round 1
// baseline (speedup 1.0000x reference)
#include <cuda_runtime.h>
#include <math_constants.h>

#define EPS_F 1e-8f
#define TOL_F 1e-6f
#define LOSS_EPS_F 1e-6f

__global__ void hx_zero_out(float* out) { out[0] = 0.0f; }

__global__ __launch_bounds__(256)
void diou3d_loss_kernel(const float* __restrict__ pred,
                        const float* __restrict__ tgt,
                        float* __restrict__ out, int n)
{
    int i = blockIdx.x * blockDim.x + threadIdx.x;
    float loss = 0.0f;
    if (i < n) {
        float p[7], t[7];
#pragma unroll
        for (int k = 0; k < 7; k++) { p[k] = pred[i * 7 + k]; t[k] = tgt[i * 7 + k]; }

        // ---- 2D corners (x, y, w, h, angle) = (p0, p1, p3, p4, p6) ----
        float c1x[4], c1y[4], c2x[4], c2y[4];
        {
            const float sx[4] = {0.5f, -0.5f, -0.5f, 0.5f};
            const float sy[4] = {0.5f, 0.5f, -0.5f, -0.5f};
            float ca = cosf(p[6]), sa = sinf(p[6]);
#pragma unroll
            for (int k = 0; k < 4; k++) {
                float x4 = sx[k] * p[3], y4 = sy[k] * p[4];
                c1x[k] = x4 * ca - y4 * sa + p[0];
                c1y[k] = x4 * sa + y4 * ca + p[1];
            }
            ca = cosf(t[6]); sa = sinf(t[6]);
#pragma unroll
            for (int k = 0; k < 4; k++) {
                float x4 = sx[k] * t[3], y4 = sy[k] * t[4];
                c2x[k] = x4 * ca - y4 * sa + t[0];
                c2y[k] = x4 * sa + y4 * ca + t[1];
            }
        }

        // ---- candidate vertex collection (valid only) ----
        float vx[24], vy[24];
        int cnt = 0;
        float sumx = 0.0f, sumy = 0.0f;

        // corners of box1 inside box2
        {
            float ax = c2x[0], ay = c2y[0];
            float abx = c2x[1] - ax, aby = c2y[1] - ay;
            float adx = c2x[3] - ax, ady = c2y[3] - ay;
            float iab = 1.0f / (abx * abx + aby * aby);
            float iad = 1.0f / (adx * adx + ady * ady);
#pragma unroll
            for (int k = 0; k < 4; k++) {
                float amx = c1x[k] - ax, amy = c1y[k] - ay;
                float pab = (abx * amx + aby * amy) * iab;
                float pad = (adx * amx + ady * amy) * iad;
                if (pab > -TOL_F && pab < 1.0f + TOL_F && pad > -TOL_F && pad < 1.0f + TOL_F) {
                    vx[cnt] = c1x[k]; vy[cnt] = c1y[k];
                    sumx += c1x[k]; sumy += c1y[k]; cnt++;
                }
            }
        }
        // corners of box2 inside box1
        {
            float ax = c1x[0], ay = c1y[0];
            float abx = c1x[1] - ax, aby = c1y[1] - ay;
            float adx = c1x[3] - ax, ady = c1y[3] - ay;
            float iab = 1.0f / (abx * abx + aby * aby);
            float iad = 1.0f / (adx * adx + ady * ady);
#pragma unroll
            for (int k = 0; k < 4; k++) {
                float amx = c2x[k] - ax, amy = c2y[k] - ay;
                float pab = (abx * amx + aby * amy) * iab;
                float pad = (adx * amx + ady * amy) * iad;
                if (pab > -TOL_F && pab < 1.0f + TOL_F && pad > -TOL_F && pad < 1.0f + TOL_F) {
                    vx[cnt] = c2x[k]; vy[cnt] = c2y[k];
                    sumx += c2x[k]; sumy += c2y[k]; cnt++;
                }
            }
        }
        // edge-edge intersections (16 pairs)
#pragma unroll
        for (int a = 0; a < 4; a++) {
            float x1 = c1x[a], y1 = c1y[a];
            float x2 = c1x[(a + 1) & 3], y2 = c1y[(a + 1) & 3];
#pragma unroll
            for (int b = 0; b < 4; b++) {
                float x3 = c2x[b], y3 = c2y[b];
                float x4 = c2x[(b + 1) & 3], y4 = c2y[(b + 1) & 3];
                float num  = (y4 - y3) * (x2 - x1) - (x4 - x3) * (y2 - y1);
                float dent = (x4 - x3) * (y1 - y3) - (y4 - y3) * (x1 - x3);
                float denu = (x2 - x1) * (y1 - y3) - (y2 - y1) * (x1 - x3);
                bool m = false;
                if (num != 0.0f) {
                    float tt = dent / num;
                    float uu = -denu / num;
                    m = (tt > 0.0f) && (tt < 1.0f) && (uu > 0.0f) && (uu < 1.0f);
                }
                if (m) {
                    float t2 = dent / (num + EPS_F);
                    float px = x1 + t2 * (x2 - x1);
                    float py = y1 + t2 * (y2 - y1);
                    vx[cnt] = px; vy[cnt] = py;
                    sumx += px; sumy += py; cnt++;
                }
            }
        }

        // ---- polygon area: sort valid vertices by angle around centroid, shoelace ----
        float area = 0.0f;
        if (cnt > 0) {
            float inv = 1.0f / (float)cnt;
            float mx = sumx * inv, my = sumy * inv;
            float ang[24];
            for (int k = 0; k < cnt; k++) {
                vx[k] -= mx; vy[k] -= my;
                ang[k] = atan2f(vy[k], vx[k]);
            }
            // stable insertion sort by angle
            for (int k = 1; k < cnt; k++) {
                float a = ang[k], x = vx[k], y = vy[k];
                int j = k - 1;
                while (j >= 0 && ang[j] > a) {
                    ang[j + 1] = ang[j]; vx[j + 1] = vx[j]; vy[j + 1] = vy[j];
                    j--;
                }
                ang[j + 1] = a; vx[j + 1] = x; vy[j + 1] = y;
            }
            float s = 0.0f;
            for (int k = 0; k < cnt; k++) {
                int k2 = (k + 1 == cnt) ? 0 : k + 1;
                s += vx[k] * vy[k2] - vy[k] * vx[k2];
            }
            area = 0.5f * fabsf(s);
        }

        // ---- 3D IoU ----
        float zmax1 = p[2] + 0.5f * p[5], zmin1 = p[2] - 0.5f * p[5];
        float zmax2 = t[2] + 0.5f * t[5], zmin2 = t[2] - 0.5f * t[5];
        float zov = fmaxf(fminf(zmax1, zmax2) - fmaxf(zmin1, zmin2), 0.0f);
        float inter3 = area * zov;
        float vol1 = p[3] * p[4] * p[5];
        float vol2 = t[3] * t[4] * t[5];
        float iou = inter3 / (vol1 + vol2 - inter3);
        if (isnan(iou)) iou = 0.0f;
        if (isinf(iou)) iou = (iou > 0.0f) ? 3.4028235e38f : -3.4028235e38f;

        // ---- center distance ----
        float d0 = p[0] - t[0], d1 = p[1] - t[1], d2 = p[2] - t[2];
        float ctd = d0 * d0 + d1 * d1 + d2 * d2;

        // ---- 3D corner distance (rotation in x-z plane) ----
        float cnd = 0.0f;
        {
            float cp = cosf(p[6]), sp = sinf(p[6]);
            float ct = cosf(t[6]), st = sinf(t[6]);
#pragma unroll
            for (int k = 0; k < 8; k++) {
                // corners_norm order: (-,-,-)(-,-,+)(-,+,+)(-,+,-)(+,-,-)(+,-,+)(+,+,+)(+,+,-)
                float gx = (k & 4) ? 0.5f : -0.5f;
                float gy = ((k == 2) | (k == 3) | (k == 6) | (k == 7)) ? 0.5f : -0.5f;
                float gz = ((k == 1) | (k == 2) | (k == 5) | (k == 6)) ? 0.5f : -0.5f;

                float xp = gx * p[3], yp = gy * p[4], zp = gz * p[5];
                float xpr = xp * cp + zp * sp + p[0];
                float ypr = yp + p[1];
                float zpr = -xp * sp + zp * cp + p[2];

                float xt = gx * t[3], yt = gy * t[4], zt = gz * t[5];
                float xtr = xt * ct + zt * st + t[0];
                float ytr = yt + t[1];
                float ztr = -xt * st + zt * ct + t[2];

                float dx = xpr - xtr, dy = ypr - ytr, dz = zpr - ztr;
                cnd += dx * dx + dy * dy + dz * dz;
            }
            cnd *= 0.125f;
        }

        float did = t[3] * t[3] + t[4] * t[4] + t[5] * t[5];
        float reg = (ctd + cnd) / (ctd + cnd + did + LOSS_EPS_F);
        loss = 1.0f - iou + reg;
    }

    // ---- block reduction + atomic ----
#pragma unroll
    for (int off = 16; off; off >>= 1)
        loss += __shfl_down_sync(0xffffffff, loss, off);

    __shared__ float warpsum[8];
    int lane = threadIdx.x & 31, wid = threadIdx.x >> 5;
    if (lane == 0) warpsum[wid] = loss;
    __syncthreads();
    if (wid == 0) {
        float s = (lane < 8) ? warpsum[lane] : 0.0f;
#pragma unroll
        for (int off = 4; off; off >>= 1)
            s += __shfl_down_sync(0xffffffff, s, off);
        if (lane == 0) atomicAdd(out, s * (1.0f / (float)n));
    }
}

extern "C" void kernel_launch(void* const* d_in, const int* in_sizes, int n_in,
                              void* d_out, int out_size)
{
    const float* pred = (const float*)d_in[0];
    const float* tgt  = (const float*)d_in[1];
    float* out = (float*)d_out;
    int n = in_sizes[0] / 7;

    hx_zero_out<<<1, 1>>>(out);
    diou3d_loss_kernel<<<(n + 255) / 256, 256>>>(pred, tgt, out, n);
}

// round 2
// speedup vs baseline: 1.2527x; 1.2527x over previous
#include <cuda_runtime.h>
#include <math_constants.h>

#define EPS_F 1e-8f
#define TOL_F 1e-6f
#define LOSS_EPS_F 1e-6f

__global__ void hx_zero_out(float* out) { out[0] = 0.0f; }

__global__ __launch_bounds__(256)
void diou3d_loss_kernel(const float* __restrict__ pred,
                        const float* __restrict__ tgt,
                        float* __restrict__ out, int n)
{
    int i = blockIdx.x * blockDim.x + threadIdx.x;
    float loss = 0.0f;
    if (i < n) {
        float p[7], t[7];
#pragma unroll
        for (int k = 0; k < 7; k++) { p[k] = pred[i * 7 + k]; t[k] = tgt[i * 7 + k]; }

        float cp, sp, ct, st;
        __sincosf(p[6], &sp, &cp);
        __sincosf(t[6], &st, &ct);

        // ---- 2D corners (x, y, w, h, angle) = (0, 1, 3, 4, 6) ----
        float c1x[4], c1y[4], c2x[4], c2y[4];
        {
            const float sx[4] = {0.5f, -0.5f, -0.5f, 0.5f};
            const float sy[4] = {0.5f, 0.5f, -0.5f, -0.5f};
#pragma unroll
            for (int k = 0; k < 4; k++) {
                float x4 = sx[k] * p[3], y4 = sy[k] * p[4];
                c1x[k] = x4 * cp - y4 * sp + p[0];
                c1y[k] = x4 * sp + y4 * cp + p[1];
                float xt = sx[k] * t[3], yt = sy[k] * t[4];
                c2x[k] = xt * ct - yt * st + t[0];
                c2y[k] = xt * st + yt * ct + t[1];
            }
        }

        // ---- candidate vertex collection (compacted; cyclic order preserved) ----
        float vx[24], vy[24];
        unsigned key[24];
        int cnt = 0;
        float sumx = 0.0f, sumy = 0.0f;

        // corners of box1 inside box2
        {
            float ax = c2x[0], ay = c2y[0];
            float abx = c2x[1] - ax, aby = c2y[1] - ay;
            float adx = c2x[3] - ax, ady = c2y[3] - ay;
            float iab = __fdividef(1.0f, abx * abx + aby * aby);
            float iad = __fdividef(1.0f, adx * adx + ady * ady);
#pragma unroll
            for (int k = 0; k < 4; k++) {
                float amx = c1x[k] - ax, amy = c1y[k] - ay;
                float pab = (abx * amx + aby * amy) * iab;
                float pad = (adx * amx + ady * amy) * iad;
                if (pab > -TOL_F && pab < 1.0f + TOL_F && pad > -TOL_F && pad < 1.0f + TOL_F) {
                    vx[cnt] = c1x[k]; vy[cnt] = c1y[k];
                    sumx += c1x[k]; sumy += c1y[k]; cnt++;
                }
            }
        }
        // corners of box2 inside box1
        {
            float ax = c1x[0], ay = c1y[0];
            float abx = c1x[1] - ax, aby = c1y[1] - ay;
            float adx = c1x[3] - ax, ady = c1y[3] - ay;
            float iab = __fdividef(1.0f, abx * abx + aby * aby);
            float iad = __fdividef(1.0f, adx * adx + ady * ady);
#pragma unroll
            for (int k = 0; k < 4; k++) {
                float amx = c2x[k] - ax, amy = c2y[k] - ay;
                float pab = (abx * amx + aby * amy) * iab;
                float pad = (adx * amx + ady * amy) * iad;
                if (pab > -TOL_F && pab < 1.0f + TOL_F && pad > -TOL_F && pad < 1.0f + TOL_F) {
                    vx[cnt] = c2x[k]; vy[cnt] = c2y[k];
                    sumx += c2x[k]; sumy += c2y[k]; cnt++;
                }
            }
        }
        // edge-edge intersections (16 pairs)
#pragma unroll
        for (int a = 0; a < 4; a++) {
            float x1 = c1x[a], y1 = c1y[a];
            float ex1 = c1x[(a + 1) & 3] - x1, ey1 = c1y[(a + 1) & 3] - y1;
#pragma unroll
            for (int b = 0; b < 4; b++) {
                float x3 = c2x[b], y3 = c2y[b];
                float ex2 = c2x[(b + 1) & 3] - x3, ey2 = c2y[(b + 1) & 3] - y3;
                float num  = ey2 * ex1 - ex2 * ey1;
                float dx13 = x1 - x3, dy13 = y1 - y3;
                float dent = ex2 * dy13 - ey2 * dx13;
                float denu = ex1 * dy13 - ey1 * dx13;
                bool m = false;
                if (num != 0.0f) {
                    float rn = __fdividef(1.0f, num);
                    float tt = dent * rn;
                    float uu = -denu * rn;
                    m = (tt > 0.0f) && (tt < 1.0f) && (uu > 0.0f) && (uu < 1.0f);
                }
                if (m) {
                    float t2 = __fdividef(dent, num + EPS_F);
                    float px = x1 + t2 * ex1;
                    float py = y1 + t2 * ey1;
                    vx[cnt] = px; vy[cnt] = py;
                    sumx += px; sumy += py; cnt++;
                }
            }
        }

        // ---- polygon area: cyclic angular order via pseudo-angle key, shoelace ----
        float area = 0.0f;
        if (cnt > 0) {
            float inv = __fdividef(1.0f, (float)cnt);
            float mx = sumx * inv, my = sumy * inv;
            for (int k = 0; k < cnt; k++) {
                float x = vx[k] - mx, y = vy[k] - my;
                vx[k] = x; vy[k] = y;
                // pseudo-angle in [0,4): monotone on the circle (cyclic order == atan2 order)
                float tt = __fdividef(x, fabsf(x) + fabsf(y) + 1e-30f);
                float a = (y >= 0.0f) ? (1.0f - tt) : (3.0f + tt);
                unsigned u = __float_as_uint(a);          // a >= 0 -> uint order == float order
                key[k] = (u & 0xFFFFFFE0u) | (unsigned)k; // idx in low 5 bits (stable ties)
            }
            // insertion sort on packed uint keys
            for (int k = 1; k < cnt; k++) {
                unsigned a = key[k];
                int j = k - 1;
                while (j >= 0 && key[j] > a) { key[j + 1] = key[j]; j--; }
                key[j + 1] = a;
            }
            // shoelace over sorted cyclic order
            unsigned k0 = key[0] & 31u;
            float fx = vx[k0], fy = vy[k0];
            float px = fx, py = fy, s = 0.0f;
            for (int k = 1; k < cnt; k++) {
                unsigned id = key[k] & 31u;
                float x = vx[id], y = vy[id];
                s += px * y - py * x;
                px = x; py = y;
            }
            s += px * fy - py * fx;
            area = 0.5f * fabsf(s);
        }

        // ---- 3D IoU ----
        float zmax1 = p[2] + 0.5f * p[5], zmin1 = p[2] - 0.5f * p[5];
        float zmax2 = t[2] + 0.5f * t[5], zmin2 = t[2] - 0.5f * t[5];
        float zov = fmaxf(fminf(zmax1, zmax2) - fmaxf(zmin1, zmin2), 0.0f);
        float inter3 = area * zov;
        float vol1 = p[3] * p[4] * p[5];
        float vol2 = t[3] * t[4] * t[5];
        float iou = inter3 / (vol1 + vol2 - inter3);
        if (isnan(iou)) iou = 0.0f;

        // ---- center distance ----
        float d0 = p[0] - t[0], d1 = p[1] - t[1], d2 = p[2] - t[2];
        float ctd = d0 * d0 + d1 * d1 + d2 * d2;

        // ---- 3D corner distance (rotation in x-z plane) ----
        float cnd = 0.0f;
        {
#pragma unroll
            for (int k = 0; k < 8; k++) {
                float gx = (k & 4) ? 0.5f : -0.5f;
                float gy = ((k == 2) | (k == 3) | (k == 6) | (k == 7)) ? 0.5f : -0.5f;
                float gz = ((k == 1) | (k == 2) | (k == 5) | (k == 6)) ? 0.5f : -0.5f;

                float xp = gx * p[3], yp = gy * p[4], zp = gz * p[5];
                float xpr = xp * cp + zp * sp + p[0];
                float ypr = yp + p[1];
                float zpr = -xp * sp + zp * cp + p[2];

                float xt = gx * t[3], yt = gy * t[4], zt = gz * t[5];
                float xtr = xt * ct + zt * st + t[0];
                float ytr = yt + t[1];
                float ztr = -xt * st + zt * ct + t[2];

                float dx = xpr - xtr, dy = ypr - ytr, dz = zpr - ztr;
                cnd += dx * dx + dy * dy + dz * dz;
            }
            cnd *= 0.125f;
        }

        float did = t[3] * t[3] + t[4] * t[4] + t[5] * t[5];
        float sreg = ctd + cnd;
        float reg = __fdividef(sreg, sreg + did + LOSS_EPS_F);
        loss = 1.0f - iou + reg;
    }

    // ---- block reduction + atomic ----
#pragma unroll
    for (int off = 16; off; off >>= 1)
        loss += __shfl_down_sync(0xffffffff, loss, off);

    __shared__ float warpsum[8];
    int lane = threadIdx.x & 31, wid = threadIdx.x >> 5;
    if (lane == 0) warpsum[wid] = loss;
    __syncthreads();
    if (wid == 0) {
        float s = (lane < 8) ? warpsum[lane] : 0.0f;
#pragma unroll
        for (int off = 4; off; off >>= 1)
            s += __shfl_down_sync(0xffffffff, s, off);
        if (lane == 0) atomicAdd(out, s * (1.0f / (float)n));
    }
}

extern "C" void kernel_launch(void* const* d_in, const int* in_sizes, int n_in,
                              void* d_out, int out_size)
{
    const float* pred = (const float*)d_in[0];
    const float* tgt  = (const float*)d_in[1];
    float* out = (float*)d_out;
    int n = in_sizes[0] / 7;

    hx_zero_out<<<1, 1>>>(out);
    diou3d_loss_kernel<<<(n + 255) / 256, 256>>>(pred, tgt, out, n);
}